// round 13
// baseline (speedup 1.0000x reference)
#include <cuda_runtime.h>
#include <cuda_bf16.h>
#include <cstdint>

// Problem shape (fixed by setup_inputs): preds [T,B,C] f32, targets [B,L] i64.
#define TT 128
#define BB 128
#define CC 8192
#define LL 50
#define NSLOT 51         // slot 0 = blank, slots 1..50 = labels
#define NSTREAM (TT*BB)  // 16384 streaming blocks

// Scratch (zero at module load; the finisher restores zeros every call; the
// launch boundary orders those stores before the next graph replay).
__device__ float    g_acc[BB * NSLOT];   // per-(b,slot) sum_t exp(x)/Z
__device__ unsigned g_done;              // global completion counter

// Fast exp on the FMA pipe (no MUFU). Rel err ~5e-5.
__device__ __forceinline__ float fast_exp(float x) {
    const float L2E = 1.4426950408889634f;
    float t  = fmaf(x, L2E, 12582912.0f);
    float nf = t - 12582912.0f;
    float f  = fmaf(x, L2E, -nf);
    int   ni = __float_as_int(t) - 0x4B400000;
    float sc = __int_as_float((ni << 23) + 0x3F800000);
    float p = fmaf(f, 0.009618129f, 0.05550411f);
    p = fmaf(f, p, 0.2402265f);
    p = fmaf(f, p, 0.6931472f);
    float fp = f * p;
    return fmaf(fp, sc, sc);
}

// Fast natural log on the FMA pipe (no MUFU). Abs err ~1e-5.
__device__ __forceinline__ float fast_logf(float a) {
    int   e = (__float_as_int(a) - 0x3f2aaaab) & 0xff800000;
    float m = __int_as_float(__float_as_int(a) - e);   // m in [2/3, 4/3)
    float i = (float)e * 1.19209290e-7f;               // e / 2^23
    float f = m - 1.0f;
    float s = f * f;
    float r = fmaf(0.230836749f, f, -0.279208571f);
    float t = fmaf(0.331826031f, f, -0.498910338f);
    r = fmaf(r, s, t);
    r = fmaf(r, s, f);
    return fmaf(i, 0.693147182f, r);
}

__device__ __forceinline__ void red_release_add(unsigned* p, unsigned v) {
    asm volatile("red.release.gpu.global.add.u32 [%0], %1;"
                 :: "l"(p), "r"(v) : "memory");
}
__device__ __forceinline__ unsigned ld_relaxed(const unsigned* p) {
    unsigned r;
    asm volatile("ld.relaxed.gpu.global.u32 %0, [%1];" : "=r"(r) : "l"(p) : "memory");
    return r;
}
__device__ __forceinline__ unsigned ld_acquire(const unsigned* p) {
    unsigned r;
    asm volatile("ld.acquire.gpu.global.u32 %0, [%1];" : "=r"(r) : "l"(p) : "memory");
    return r;
}

// ---------------------------------------------------------------------------
// Blocks [0, NSTREAM): exact R10 stream (label -> early gather -> 32 KB
// stream -> Z -> relaxed REDGs) + ONE fire-and-forget red.release on g_done.
// Block NSTREAM (scheduled last, during the drain -> zero stream-occupancy
// cost): spins for g_done == NSTREAM, acquires, then does the whole epilogue
// with one thread-pair per b (high-MLP L2-hot loads), single plain STG out.
// ---------------------------------------------------------------------------
__global__ __launch_bounds__(256) void ace_kernel(
    const float* __restrict__ preds,
    const long long* __restrict__ tgt,
    float* __restrict__ out)
{
    int blk = blockIdx.x;
    int tid = threadIdx.x;

    if (blk < NSTREAM) {
        // ================= streaming path =================================
        int b = blk & (BB - 1);
        const float* rowf = preds + (size_t)blk * CC;

        int c = 0;                        // slot 0 -> blank class 0
        if (tid >= 1 && tid < NSLOT) {
            long long l = tgt[(size_t)b * LL + (tid - 1)];
            if (l > 0 && l < CC) c = (int)l;
        }
        float xc = 0.0f;
        if (tid < NSLOT) xc = __ldg(rowf + c);   // in flight during stream

        const float4* row = reinterpret_cast<const float4*>(rowf);
        float acc = 0.0f;
#pragma unroll
        for (int i = 0; i < 8; i++) {
            float4 v = row[tid + i * 256];       // 8 front-batched LDG.128
            acc += fast_exp(v.x) + fast_exp(v.y) + fast_exp(v.z) + fast_exp(v.w);
        }
#pragma unroll
        for (int o = 16; o > 0; o >>= 1)
            acc += __shfl_xor_sync(0xFFFFFFFFu, acc, o);

        __shared__ float s[8];
        if ((tid & 31) == 0) s[tid >> 5] = acc;
        __syncthreads();

        if (tid < NSLOT) {
            float z = s[0] + s[1] + s[2] + s[3] + s[4] + s[5] + s[6] + s[7];
            atomicAdd(&g_acc[b * NSLOT + tid], fast_exp(xc) * (1.0f / z));
        }

        __syncthreads();                  // block's REDGs precede the release
        if (tid == 0) red_release_add(&g_done, 1u);
        return;
    }

    // ===================== single finisher block ==========================
    // Thread layout: b = tid>>1, half = tid&1.
    //   half 0: slots 0..25  (labels 0..24 for slots 1..25)
    //   half 1: slots 26..50 (labels 25..49)
    int b    = tid >> 1;
    int half = tid & 1;
    int lab0 = half ? 25 : 0;             // first label index this thread owns
    int nlab = 25;

    // Pre-spin: load labels (input array, L2-hot from streamers) + weights.
    float w[26];
    float npos_part = 0.0f;
    {
        int base = b * LL + lab0;
#pragma unroll
        for (int j = 0; j < 25; j++) {
            long long l = tgt[base + j];
            float v = (l > 0 && l < CC) ? 1.0f : 0.0f;
            w[half ? j : j + 1] = v;      // label j -> slot lab0+j+1
            npos_part += v;
        }
        (void)nlab;
    }
    // npos = own part + partner's (adjacent lane, same warp).
    float npos = npos_part + __shfl_xor_sync(0xFFFFFFFFu, npos_part, 1);
    if (half == 0) w[0] = (float)TT - npos;         // blank weight in slot 0

    // Wait for all streamers.
    __shared__ unsigned s_go;
    if (tid == 0) {
        while (ld_relaxed(&g_done) != NSTREAM) __nanosleep(64);
        (void)ld_acquire(&g_done);        // sync with the release sequence
        s_go = 1;
    }
    __syncthreads();

    // Epilogue: nslots independent L2-hot loads (MLP hides latency).
    int slot0  = half ? 26 : 0;
    int nslots = half ? 25 : 26;
    const float LOG_T = 4.852030263919617f;         // ln(128)
    float lsum = 0.0f;
    {
        int base = b * NSLOT + slot0;
        float tot[26];
#pragma unroll
        for (int j = 0; j < 26; j++)
            if (j < nslots) tot[j] = g_acc[base + j];
#pragma unroll
        for (int j = 0; j < 26; j++)
            if (j < nslots) {
                g_acc[base + j] = 0.0f;   // restore invariant for next replay
                if (w[j] != 0.0f) lsum += w[j] * (fast_logf(tot[j]) - LOG_T);
            }
    }

    // Block reduce 256 -> 1, single plain store (out needs no pre-zero).
#pragma unroll
    for (int o = 16; o > 0; o >>= 1)
        lsum += __shfl_xor_sync(0xFFFFFFFFu, lsum, o);
    __shared__ float sred[8];
    if ((tid & 31) == 0) sred[tid >> 5] = lsum;
    __syncthreads();
    if (tid == 0) {
        float v = sred[0] + sred[1] + sred[2] + sred[3]
                + sred[4] + sred[5] + sred[6] + sred[7];
        *out = -v * (1.0f / ((float)BB * (float)TT));
        g_done = 0u;                      // restore invariant for next replay
    }
}

extern "C" void kernel_launch(void* const* d_in, const int* in_sizes, int n_in,
                              void* d_out, int out_size)
{
    const float*     preds = (const float*)d_in[0];
    const long long* tgt   = (const long long*)d_in[1];
    float*           out   = (float*)d_out;

    ace_kernel<<<NSTREAM + 1, 256>>>(preds, tgt, out);
}